// round 3
// baseline (speedup 1.0000x reference)
#include <cuda_runtime.h>
#include <math.h>

// ---------------- problem constants ----------------
#define NYI   300
#define NXI   300
#define PML_W 20
#define NYP   340
#define NXP   340
#define NT    128
#define NSHOT 2
#define NREC  32
#define DT_F    0.001f
#define INV_DX  0.2f
#define C1F     1.125f
#define C2F     (-1.0f/24.0f)

// ---------------- tiling ----------------
#define TS    8                       // 8x8 tiles per shot
#define TILE  43                      // ceil(340/8)
#define NB    (NSHOT*TS*TS)           // 128 CTAs
#define NTHR  512
#define SP    49                      // smem row pitch (floats), odd vs 32 banks
#define SROWS 47                      // TILE + 4 halo rows
#define FSZ   (SROWS*SP)              // 2303 floats per field
#define NFIELDS 13
#define SMEM_BYTES (NFIELDS*FSZ*4)    // 119756 B

// field ids in smem
enum {F_VY=0,F_VX,F_SYY,F_SXX,F_SXY,F_MVYY,F_MVYX,F_MVXY,F_MVXX,F_MSYYY,F_MSXYX,F_MSXYY,F_MSXXX};

// ---------------- exchange buffers ----------------
// layout: [cta][side(0N,1S,2W,3E)][field slot 0..4][2][43]
#define XLEN  (4*5*2*43)
__device__ float g_xch[NB*XLEN];
__device__ int   g_flag[NB];

#define XPTR(cta, side, f) (g_xch + (((cta)*4 + (side))*5 + (f))*86)

__global__ void k_init()
{
    if (threadIdx.x < NB) g_flag[threadIdx.x] = 0;
}

__device__ __forceinline__ float pml_b(int u)
{
    double d0 = 414.4653366865718;   // 3*2000/(2*20*5) * ln(1e6)
    double lo = (20.0 - (double)u) / 20.0; lo = lo < 0.0 ? 0.0 : (lo > 1.0 ? 1.0 : lo);
    double hi = ((double)u - 319.0) / 20.0; hi = hi < 0.0 ? 0.0 : (hi > 1.0 ? 1.0 : hi);
    double mm = lo > hi ? lo : hi;
    return (float)exp(-d0 * mm * mm * 0.001);
}

// publish my epoch, wait for neighbors to reach it
__device__ __forceinline__ void publish_and_wait(int me, int e,
                                                 bool hN, bool hS, bool hW, bool hE, int tid)
{
    __threadfence();          // drain my strip stores to L2 (order before flag)
    __syncthreads();
    if (tid == 0)  atomicExch(&g_flag[me], e);
    if (tid == 32 && hN){ volatile int* f = &g_flag[me-TS]; while (*f < e) __nanosleep(20); }
    if (tid == 64 && hS){ volatile int* f = &g_flag[me+TS]; while (*f < e) __nanosleep(20); }
    if (tid == 96 && hW){ volatile int* f = &g_flag[me-1 ]; while (*f < e) __nanosleep(20); }
    if (tid ==128 && hE){ volatile int* f = &g_flag[me+1 ]; while (*f < e) __nanosleep(20); }
    __syncthreads();
}

// write my boundary strips of field F (smem) to my exchange slot f
__device__ __forceinline__ void write_strips(const float* F, int me, int f,
                                             int th, int tw,
                                             bool hN, bool hS, bool hW, bool hE,
                                             int tid, bool doNS, bool doWE)
{
    if (doNS && hN && tid < tw){
        float* p = XPTR(me, 0, f);
        p[tid]      = F[2*SP + tid + 2];
        p[43 + tid] = F[3*SP + tid + 2];
    }
    if (doNS && hS && tid < tw){
        float* p = XPTR(me, 1, f);
        p[tid]      = F[ th   *SP + tid + 2];
        p[43 + tid] = F[(th+1)*SP + tid + 2];
    }
    if (doWE && hW && tid < th){
        float* p = XPTR(me, 2, f);
        p[tid]      = F[(tid+2)*SP + 2];
        p[43 + tid] = F[(tid+2)*SP + 3];
    }
    if (doWE && hE && tid < th){
        float* p = XPTR(me, 3, f);
        p[tid]      = F[(tid+2)*SP + tw];
        p[43 + tid] = F[(tid+2)*SP + tw + 1];
    }
}

// read neighbor strips into my halo region of field F
__device__ __forceinline__ void read_halos(float* F, int me, int f,
                                           int th, int tw,
                                           bool hN, bool hS, bool hW, bool hE,
                                           int tid, bool doNS, bool doWE)
{
    if (doNS && hN && tid < tw){
        const float* q = XPTR(me - TS, 1, f);     // north nb's south strip
        F[0*SP + tid + 2] = __ldcg(q + tid);
        F[1*SP + tid + 2] = __ldcg(q + 43 + tid);
    }
    if (doNS && hS && tid < tw){
        const float* q = XPTR(me + TS, 0, f);     // south nb's north strip
        F[(th+2)*SP + tid + 2] = __ldcg(q + tid);
        F[(th+3)*SP + tid + 2] = __ldcg(q + 43 + tid);
    }
    if (doWE && hW && tid < th){
        const float* q = XPTR(me - 1, 3, f);      // west nb's east strip
        F[(tid+2)*SP + 0] = __ldcg(q + tid);
        F[(tid+2)*SP + 1] = __ldcg(q + 43 + tid);
    }
    if (doWE && hE && tid < th){
        const float* q = XPTR(me + 1, 2, f);      // east nb's west strip
        F[(tid+2)*SP + tw + 2] = __ldcg(q + tid);
        F[(tid+2)*SP + tw + 3] = __ldcg(q + 43 + tid);
    }
}

__global__ void __launch_bounds__(NTHR, 1)
k_main(const float* __restrict__ lamb,
       const float* __restrict__ muv,
       const float* __restrict__ buov,
       const float* __restrict__ amp,    // [NSHOT,1,NT]
       const int*   __restrict__ sloc,   // [NSHOT,1,2]
       const int*   __restrict__ rloc,   // [NSHOT,NREC,2]
       float*       __restrict__ out)    // [NSHOT,NREC,NT]
{
    extern __shared__ float sm[];
    const int tid  = threadIdx.x;
    const int me   = blockIdx.x;
    const int shot = me >> 6;
    const int tile = me & 63;
    const int ty   = tile >> 3, tx = tile & 7;
    const int y0   = ty * TILE, x0 = tx * TILE;
    const int th   = (y0 + TILE <= NYP) ? TILE : (NYP - y0);
    const int tw   = (x0 + TILE <= NXP) ? TILE : (NXP - x0);
    const bool hN = (ty > 0), hS = (ty < TS-1), hW = (tx > 0), hE = (tx < TS-1);

    float* SVY    = sm + F_VY   *FSZ;
    float* SVX    = sm + F_VX   *FSZ;
    float* SSYY   = sm + F_SYY  *FSZ;
    float* SSXX   = sm + F_SXX  *FSZ;
    float* SSXY   = sm + F_SXY  *FSZ;
    float* SMVYY  = sm + F_MVYY *FSZ;
    float* SMVYX  = sm + F_MVYX *FSZ;
    float* SMVXY  = sm + F_MVXY *FSZ;
    float* SMVXX  = sm + F_MVXX *FSZ;
    float* SMSYYY = sm + F_MSYYY*FSZ;
    float* SMSXYX = sm + F_MSXYX*FSZ;
    float* SMSXYY = sm + F_MSXYY*FSZ;
    float* SMSXXX = sm + F_MSXXX*FSZ;

    // zero all smem fields (incl. halos)
    for (int i = tid; i < NFIELDS*FSZ; i += NTHR) sm[i] = 0.0f;

    // source cell (padded coords)
    const int sy = sloc[shot*2 + 0] + PML_W;
    const int sx = sloc[shot*2 + 1] + PML_W;

    // per-thread cell list (max 4 cells: 43*43/512 < 4)
    int   nc = 0;
    int   soff[4]; float cby[4], cbx[4], cbuo[4], clam[4], clp2m[4], cmu[4];
    bool  csrc[4];
    for (int idx = tid; idx < th*tw && nc < 4; idx += NTHR){
        int li = idx / tw, lj = idx % tw;
        int gy = y0 + li, gx = x0 + lj;
        int iy = gy - PML_W; iy = iy < 0 ? 0 : (iy > NYI-1 ? NYI-1 : iy);
        int ix = gx - PML_W; ix = ix < 0 ? 0 : (ix > NXI-1 ? NXI-1 : ix);
        float l = lamb[iy*NXI + ix];
        float m = muv [iy*NXI + ix];
        soff[nc]  = (li+2)*SP + (lj+2);
        cby[nc]   = pml_b(gy);
        cbx[nc]   = pml_b(gx);
        cbuo[nc]  = buov[iy*NXI + ix];
        clam[nc]  = l;
        clp2m[nc] = l + 2.0f*m;
        cmu[nc]   = m;
        csrc[nc]  = (gy == sy && gx == sx);
        nc++;
    }

    // receiver ownership (64 receivers, thread tid<64 checks receiver tid)
    int rsoff = -1, rout = -1;
    if (tid < NSHOT*NREC){
        int rs = tid >> 5;
        int ry = rloc[tid*2 + 0] + PML_W;
        int rx = rloc[tid*2 + 1] + PML_W;
        if (rs == shot && ry >= y0 && ry < y0 + th && rx >= x0 && rx < x0 + tw){
            rsoff = (ry - y0 + 2)*SP + (rx - x0 + 2);
            rout  = tid*NT;
        }
    }
    __syncthreads();

    for (int t = 0; t < NT; t++){
        // ================= V phase: velocity update =================
        float srcamp = 0.0f;
        // any thread might own source; load once per step (L1-resident)
        srcamp = amp[shot*NT + t];
#pragma unroll
        for (int k = 0; k < 4; k++) if (k < nc){
            const int o = soff[k];
            const float byk = cby[k], bxk = cbx[k];
            float d, m, t1, t2;
            // d_plus(syy, y)
            d = (C1F*(SSYY[o+SP]-SSYY[o]) + C2F*(SSYY[o+2*SP]-SSYY[o-SP]))*INV_DX;
            t1 = d;
            if (byk != 1.0f){ m = SMSYYY[o]; m = byk*m + (byk-1.0f)*d; SMSYYY[o] = m; t1 += m; }
            // d_minus(sxy, x)
            d = (C1F*(SSXY[o]-SSXY[o-1]) + C2F*(SSXY[o+1]-SSXY[o-2]))*INV_DX;
            t2 = d;
            if (bxk != 1.0f){ m = SMSXYX[o]; m = bxk*m + (bxk-1.0f)*d; SMSXYX[o] = m; t2 += m; }
            float nvy = SVY[o] + DT_F*cbuo[k]*(t1 + t2);
            if (csrc[k]) nvy += srcamp;
            SVY[o] = nvy;
            // d_minus(sxy, y)
            d = (C1F*(SSXY[o]-SSXY[o-SP]) + C2F*(SSXY[o+SP]-SSXY[o-2*SP]))*INV_DX;
            t1 = d;
            if (byk != 1.0f){ m = SMSXYY[o]; m = byk*m + (byk-1.0f)*d; SMSXYY[o] = m; t1 += m; }
            // d_plus(sxx, x)
            d = (C1F*(SSXX[o+1]-SSXX[o]) + C2F*(SSXX[o+2]-SSXX[o-1]))*INV_DX;
            t2 = d;
            if (bxk != 1.0f){ m = SMSXXX[o]; m = bxk*m + (bxk-1.0f)*d; SMSXXX[o] = m; t2 += m; }
            SVX[o] += DT_F*cbuo[k]*(t1 + t2);
        }
        __syncthreads();

        // receivers record vy (stable through S phase)
        if (rout >= 0) out[rout + t] = SVY[rsoff];

        // export vy, vx strips
        write_strips(SVY, me, 0, th, tw, hN, hS, hW, hE, tid, true, true);
        write_strips(SVX, me, 1, th, tw, hN, hS, hW, hE, tid, true, true);
        publish_and_wait(me, 2*t + 1, hN, hS, hW, hE, tid);
        // import neighbor vy, vx halos
        read_halos(SVY, me, 0, th, tw, hN, hS, hW, hE, tid, true, true);
        read_halos(SVX, me, 1, th, tw, hN, hS, hW, hE, tid, true, true);
        __syncthreads();

        // ================= S phase: stress update =================
#pragma unroll
        for (int k = 0; k < 4; k++) if (k < nc){
            const int o = soff[k];
            const float byk = cby[k], bxk = cbx[k];
            float d, m;
            // d_minus(vy, y)
            d = (C1F*(SVY[o]-SVY[o-SP]) + C2F*(SVY[o+SP]-SVY[o-2*SP]))*INV_DX;
            float dyy = d;
            if (byk != 1.0f){ m = SMVYY[o]; m = byk*m + (byk-1.0f)*d; SMVYY[o] = m; dyy += m; }
            // d_minus(vx, x)
            d = (C1F*(SVX[o]-SVX[o-1]) + C2F*(SVX[o+1]-SVX[o-2]))*INV_DX;
            float dxx = d;
            if (bxk != 1.0f){ m = SMVXX[o]; m = bxk*m + (bxk-1.0f)*d; SMVXX[o] = m; dxx += m; }
            SSYY[o] += DT_F*(clp2m[k]*dyy + clam[k]*dxx);
            SSXX[o] += DT_F*(clp2m[k]*dxx + clam[k]*dyy);
            // d_plus(vy, x)
            d = (C1F*(SVY[o+1]-SVY[o]) + C2F*(SVY[o+2]-SVY[o-1]))*INV_DX;
            float dyx = d;
            if (bxk != 1.0f){ m = SMVYX[o]; m = bxk*m + (bxk-1.0f)*d; SMVYX[o] = m; dyx += m; }
            // d_plus(vx, y)
            d = (C1F*(SVX[o+SP]-SVX[o]) + C2F*(SVX[o+2*SP]-SVX[o-SP]))*INV_DX;
            float dxy = d;
            if (byk != 1.0f){ m = SMVXY[o]; m = byk*m + (byk-1.0f)*d; SMVXY[o] = m; dxy += m; }
            SSXY[o] += DT_F*cmu[k]*(dyx + dxy);
        }
        __syncthreads();

        // export stress strips (syy: N/S only; sxx: W/E only; sxy: all)
        write_strips(SSYY, me, 2, th, tw, hN, hS, hW, hE, tid, true,  false);
        write_strips(SSXX, me, 3, th, tw, hN, hS, hW, hE, tid, false, true );
        write_strips(SSXY, me, 4, th, tw, hN, hS, hW, hE, tid, true,  true );
        publish_and_wait(me, 2*t + 2, hN, hS, hW, hE, tid);
        read_halos(SSYY, me, 2, th, tw, hN, hS, hW, hE, tid, true,  false);
        read_halos(SSXX, me, 3, th, tw, hN, hS, hW, hE, tid, false, true );
        read_halos(SSXY, me, 4, th, tw, hN, hS, hW, hE, tid, true,  true );
        __syncthreads();
    }
}

// ---------------- launch ----------------
extern "C" void kernel_launch(void* const* d_in, const int* in_sizes, int n_in,
                              void* d_out, int out_size)
{
    const float* lamb = (const float*)d_in[0];
    const float* mu   = (const float*)d_in[1];
    const float* buo  = (const float*)d_in[2];
    const float* amp  = (const float*)d_in[3];
    const int*   sloc = (const int*)  d_in[4];
    const int*   rloc = (const int*)  d_in[5];
    float* out = (float*)d_out;

    static bool attr_set = false;
    if (!attr_set){
        cudaFuncSetAttribute(k_main, cudaFuncAttributeMaxDynamicSharedMemorySize, SMEM_BYTES);
        attr_set = true;
    }

    k_init<<<1, 128>>>();
    k_main<<<NB, NTHR, SMEM_BYTES>>>(lamb, mu, buo, amp, sloc, rloc, out);
}

// round 4
// speedup vs baseline: 1.1180x; 1.1180x over previous
#include <cuda_runtime.h>
#include <math.h>

// ---------------- problem constants ----------------
#define NYI   300
#define NXI   300
#define PML_W 20
#define NYP   340
#define NXP   340
#define NT    128
#define NSHOT 2
#define NREC  32
#define DT_F    0.001f
#define INV_DX  0.2f
#define C1F     1.125f
#define C2F     (-1.0f/24.0f)

// ---------------- tiling ----------------
#define TS    8                       // 8x8 tiles per shot
#define TILE  43                      // ceil(340/8)
#define NB    (NSHOT*TS*TS)           // 128 CTAs
#define NTHR  512
#define SP    49                      // smem row pitch (floats)
#define SROWS 47                      // TILE + 4 halo rows
#define FSZ   (SROWS*SP)              // 2303 floats per field
#define NFIELDS 13
#define SMEM_BYTES (NFIELDS*FSZ*4)    // 119756 B

enum {F_VY=0,F_VX,F_SYY,F_SXX,F_SXY,F_MVYY,F_MVYX,F_MVXY,F_MVXX,F_MSYYY,F_MSXYX,F_MSXYY,F_MSXXX};

// ---------------- exchange buffers ----------------
#define XLEN  (4*5*2*43)
__device__ float g_xch[NB*XLEN];
__device__ int   g_flag[NB];

#define XPTR(cta, side, f) (g_xch + (((cta)*4 + (side))*5 + (f))*86)

__global__ void k_init()
{
    if (threadIdx.x < NB) g_flag[threadIdx.x] = 0;
}

__device__ __forceinline__ float pml_b(int u)
{
    double d0 = 414.4653366865718;   // 3*2000/(2*20*5) * ln(1e6)
    double lo = (20.0 - (double)u) / 20.0; lo = lo < 0.0 ? 0.0 : (lo > 1.0 ? 1.0 : lo);
    double hi = ((double)u - 319.0) / 20.0; hi = hi < 0.0 ? 0.0 : (hi > 1.0 ? 1.0 : hi);
    double mm = lo > hi ? lo : hi;
    return (float)exp(-d0 * mm * mm * 0.001);
}

// ---------------- strip export / halo import ----------------
__device__ __forceinline__ void write_strips(const float* F, int me, int f,
                                             int th, int tw,
                                             bool hN, bool hS, bool hW, bool hE,
                                             int tid, bool doNS, bool doWE)
{
    if (doNS && hN && tid < tw){
        float* p = XPTR(me, 0, f);
        p[tid]      = F[2*SP + tid + 2];
        p[43 + tid] = F[3*SP + tid + 2];
    }
    if (doNS && hS && tid < tw){
        float* p = XPTR(me, 1, f);
        p[tid]      = F[ th   *SP + tid + 2];
        p[43 + tid] = F[(th+1)*SP + tid + 2];
    }
    if (doWE && hW && tid < th){
        float* p = XPTR(me, 2, f);
        p[tid]      = F[(tid+2)*SP + 2];
        p[43 + tid] = F[(tid+2)*SP + 3];
    }
    if (doWE && hE && tid < th){
        float* p = XPTR(me, 3, f);
        p[tid]      = F[(tid+2)*SP + tw];
        p[43 + tid] = F[(tid+2)*SP + tw + 1];
    }
}

__device__ __forceinline__ void read_halos(float* F, int me, int f,
                                           int th, int tw,
                                           bool hN, bool hS, bool hW, bool hE,
                                           int tid, bool doNS, bool doWE)
{
    if (doNS && hN && tid < tw){
        const float* q = XPTR(me - TS, 1, f);
        F[0*SP + tid + 2] = __ldcg(q + tid);
        F[1*SP + tid + 2] = __ldcg(q + 43 + tid);
    }
    if (doNS && hS && tid < tw){
        const float* q = XPTR(me + TS, 0, f);
        F[(th+2)*SP + tid + 2] = __ldcg(q + tid);
        F[(th+3)*SP + tid + 2] = __ldcg(q + 43 + tid);
    }
    if (doWE && hW && tid < th){
        const float* q = XPTR(me - 1, 3, f);
        F[(tid+2)*SP + 0] = __ldcg(q + tid);
        F[(tid+2)*SP + 1] = __ldcg(q + 43 + tid);
    }
    if (doWE && hE && tid < th){
        const float* q = XPTR(me + 1, 2, f);
        F[(tid+2)*SP + tw + 2] = __ldcg(q + tid);
        F[(tid+2)*SP + tw + 3] = __ldcg(q + 43 + tid);
    }
}

// ---------------- per-cell physics ----------------
struct CellP { int o; float by, bx, buo, lam, lp2m, mu; bool src; };

__device__ __forceinline__ void cellV(const CellP& c, float srcamp,
    float* SVY, float* SVX, const float* SSYY, const float* SSXX, const float* SSXY,
    float* SMSYYY, float* SMSXYX, float* SMSXYY, float* SMSXXX)
{
    const int o = c.o;
    const float byk = c.by, bxk = c.bx;
    float d, m, t1, t2;
    d = (C1F*(SSYY[o+SP]-SSYY[o]) + C2F*(SSYY[o+2*SP]-SSYY[o-SP]))*INV_DX;
    t1 = d;
    if (byk != 1.0f){ m = SMSYYY[o]; m = byk*m + (byk-1.0f)*d; SMSYYY[o] = m; t1 += m; }
    d = (C1F*(SSXY[o]-SSXY[o-1]) + C2F*(SSXY[o+1]-SSXY[o-2]))*INV_DX;
    t2 = d;
    if (bxk != 1.0f){ m = SMSXYX[o]; m = bxk*m + (bxk-1.0f)*d; SMSXYX[o] = m; t2 += m; }
    float nvy = SVY[o] + DT_F*c.buo*(t1 + t2);
    if (c.src) nvy += srcamp;
    SVY[o] = nvy;
    d = (C1F*(SSXY[o]-SSXY[o-SP]) + C2F*(SSXY[o+SP]-SSXY[o-2*SP]))*INV_DX;
    t1 = d;
    if (byk != 1.0f){ m = SMSXYY[o]; m = byk*m + (byk-1.0f)*d; SMSXYY[o] = m; t1 += m; }
    d = (C1F*(SSXX[o+1]-SSXX[o]) + C2F*(SSXX[o+2]-SSXX[o-1]))*INV_DX;
    t2 = d;
    if (bxk != 1.0f){ m = SMSXXX[o]; m = bxk*m + (bxk-1.0f)*d; SMSXXX[o] = m; t2 += m; }
    SVX[o] += DT_F*c.buo*(t1 + t2);
}

__device__ __forceinline__ void cellS(const CellP& c,
    const float* SVY, const float* SVX, float* SSYY, float* SSXX, float* SSXY,
    float* SMVYY, float* SMVYX, float* SMVXY, float* SMVXX)
{
    const int o = c.o;
    const float byk = c.by, bxk = c.bx;
    float d, m;
    d = (C1F*(SVY[o]-SVY[o-SP]) + C2F*(SVY[o+SP]-SVY[o-2*SP]))*INV_DX;
    float dyy = d;
    if (byk != 1.0f){ m = SMVYY[o]; m = byk*m + (byk-1.0f)*d; SMVYY[o] = m; dyy += m; }
    d = (C1F*(SVX[o]-SVX[o-1]) + C2F*(SVX[o+1]-SVX[o-2]))*INV_DX;
    float dxx = d;
    if (bxk != 1.0f){ m = SMVXX[o]; m = bxk*m + (bxk-1.0f)*d; SMVXX[o] = m; dxx += m; }
    SSYY[o] += DT_F*(c.lp2m*dyy + c.lam*dxx);
    SSXX[o] += DT_F*(c.lp2m*dxx + c.lam*dyy);
    d = (C1F*(SVY[o+1]-SVY[o]) + C2F*(SVY[o+2]-SVY[o-1]))*INV_DX;
    float dyx = d;
    if (bxk != 1.0f){ m = SMVYX[o]; m = bxk*m + (bxk-1.0f)*d; SMVYX[o] = m; dyx += m; }
    d = (C1F*(SVX[o+SP]-SVX[o]) + C2F*(SVX[o+2*SP]-SVX[o-SP]))*INV_DX;
    float dxy = d;
    if (byk != 1.0f){ m = SMVXY[o]; m = byk*m + (byk-1.0f)*d; SMVXY[o] = m; dxy += m; }
    SSXY[o] += DT_F*c.mu*(dyx + dxy);
}

__global__ void __launch_bounds__(NTHR, 1)
k_main(const float* __restrict__ lamb,
       const float* __restrict__ muv,
       const float* __restrict__ buov,
       const float* __restrict__ amp,    // [NSHOT,1,NT]
       const int*   __restrict__ sloc,   // [NSHOT,1,2]
       const int*   __restrict__ rloc,   // [NSHOT,NREC,2]
       float*       __restrict__ out)    // [NSHOT,NREC,NT]
{
    extern __shared__ float sm[];
    const int tid  = threadIdx.x;
    const int me   = blockIdx.x;
    const int shot = me >> 6;
    const int tile = me & 63;
    const int ty   = tile >> 3, tx = tile & 7;
    const int y0   = ty * TILE, x0 = tx * TILE;
    const int th   = (y0 + TILE <= NYP) ? TILE : (NYP - y0);
    const int tw   = (x0 + TILE <= NXP) ? TILE : (NXP - x0);
    const bool hN = (ty > 0), hS = (ty < TS-1), hW = (tx > 0), hE = (tx < TS-1);

    float* SVY    = sm + F_VY   *FSZ;
    float* SVX    = sm + F_VX   *FSZ;
    float* SSYY   = sm + F_SYY  *FSZ;
    float* SSXX   = sm + F_SXX  *FSZ;
    float* SSXY   = sm + F_SXY  *FSZ;
    float* SMVYY  = sm + F_MVYY *FSZ;
    float* SMVYX  = sm + F_MVYX *FSZ;
    float* SMVXY  = sm + F_MVXY *FSZ;
    float* SMVXX  = sm + F_MVXX *FSZ;
    float* SMSYYY = sm + F_MSYYY*FSZ;
    float* SMSXYX = sm + F_MSXYX*FSZ;
    float* SMSXYY = sm + F_MSXYY*FSZ;
    float* SMSXXX = sm + F_MSXXX*FSZ;

    for (int i = tid; i < NFIELDS*FSZ; i += NTHR) sm[i] = 0.0f;

    const int sy = sloc[shot*2 + 0] + PML_W;
    const int sx = sloc[shot*2 + 1] + PML_W;

    // ---- boundary ring cell (<=1 per thread): 2-wide frame of the tile ----
    CellP bc; bool hasB = false;
    {
        const int nbc = 4*tw + 4*(th-4);
        if (tid < nbc){
            int li, lj;
            if (tid < 2*tw){ li = tid / tw; lj = tid % tw; }
            else if (tid < 4*tw){ int q = tid - 2*tw; li = th-2 + q / tw; lj = q % tw; }
            else {
                int q = tid - 4*tw;
                int half = 2*(th-4);
                int side = q / half;         // 0 = left cols, 1 = right cols
                int r = q % half;
                li = 2 + (r >> 1);
                lj = side == 0 ? (r & 1) : tw-2 + (r & 1);
            }
            int gy = y0 + li, gx = x0 + lj;
            int iy = gy - PML_W; iy = iy < 0 ? 0 : (iy > NYI-1 ? NYI-1 : iy);
            int ix = gx - PML_W; ix = ix < 0 ? 0 : (ix > NXI-1 ? NXI-1 : ix);
            float l = lamb[iy*NXI + ix], m = muv[iy*NXI + ix];
            bc.o = (li+2)*SP + (lj+2);
            bc.by = pml_b(gy); bc.bx = pml_b(gx);
            bc.buo = buov[iy*NXI + ix];
            bc.lam = l; bc.lp2m = l + 2.0f*m; bc.mu = m;
            bc.src = (gy == sy && gx == sx);
            hasB = true;
        }
    }

    // ---- interior cells (<=3 per thread): [2, th-2) x [2, tw-2) ----
    CellP ic[3]; int ncI = 0;
    {
        const int ih = th - 4, iw = tw - 4;
        const int nint = ih * iw;
#pragma unroll
        for (int k = 0; k < 3; k++){
            int idx = tid + k*NTHR;
            if (idx < nint){
                int li = 2 + idx / iw, lj = 2 + idx % iw;
                int gy = y0 + li, gx = x0 + lj;
                int iy = gy - PML_W; iy = iy < 0 ? 0 : (iy > NYI-1 ? NYI-1 : iy);
                int ix = gx - PML_W; ix = ix < 0 ? 0 : (ix > NXI-1 ? NXI-1 : ix);
                float l = lamb[iy*NXI + ix], m = muv[iy*NXI + ix];
                ic[ncI].o = (li+2)*SP + (lj+2);
                ic[ncI].by = pml_b(gy); ic[ncI].bx = pml_b(gx);
                ic[ncI].buo = buov[iy*NXI + ix];
                ic[ncI].lam = l; ic[ncI].lp2m = l + 2.0f*m; ic[ncI].mu = m;
                ic[ncI].src = (gy == sy && gx == sx);
                ncI++;
            }
        }
    }

    // receiver ownership
    int rsoff = -1, rout = -1;
    if (tid < NSHOT*NREC){
        int rs = tid >> 5;
        int ry = rloc[tid*2 + 0] + PML_W;
        int rx = rloc[tid*2 + 1] + PML_W;
        if (rs == shot && ry >= y0 && ry < y0 + th && rx >= x0 && rx < x0 + tw){
            rsoff = (ry - y0 + 2)*SP + (rx - x0 + 2);
            rout  = tid*NT;
        }
    }
    __syncthreads();

    for (int t = 0; t < NT; t++){
        const float srcamp = amp[shot*NT + t];

        // ================= V phase =================
        if (hasB) cellV(bc, srcamp, SVY, SVX, SSYY, SSXX, SSXY, SMSYYY, SMSXYX, SMSXYY, SMSXXX);
        __syncthreads();

        // publish boundary early, compute interior to hide the round trips
        write_strips(SVY, me, 0, th, tw, hN, hS, hW, hE, tid, true, true);
        write_strips(SVX, me, 1, th, tw, hN, hS, hW, hE, tid, true, true);
        if (tid < 64) __threadfence();
        __syncthreads();
        if (tid == 0) atomicExch(&g_flag[me], 2*t + 1);

#pragma unroll
        for (int k = 0; k < 3; k++) if (k < ncI)
            cellV(ic[k], srcamp, SVY, SVX, SSYY, SSXX, SSXY, SMSYYY, SMSXYX, SMSXYY, SMSXXX);

        if (tid == 32 && hN){ volatile int* f = &g_flag[me-TS]; while (*f < 2*t+1) {} }
        if (tid == 64 && hS){ volatile int* f = &g_flag[me+TS]; while (*f < 2*t+1) {} }
        if (tid == 96 && hW){ volatile int* f = &g_flag[me-1 ]; while (*f < 2*t+1) {} }
        if (tid ==128 && hE){ volatile int* f = &g_flag[me+1 ]; while (*f < 2*t+1) {} }
        __syncthreads();

        read_halos(SVY, me, 0, th, tw, hN, hS, hW, hE, tid, true, true);
        read_halos(SVX, me, 1, th, tw, hN, hS, hW, hE, tid, true, true);
        __syncthreads();

        if (rout >= 0) out[rout + t] = SVY[rsoff];

        // ================= S phase =================
        if (hasB) cellS(bc, SVY, SVX, SSYY, SSXX, SSXY, SMVYY, SMVYX, SMVXY, SMVXX);
        __syncthreads();

        write_strips(SSYY, me, 2, th, tw, hN, hS, hW, hE, tid, true,  false);
        write_strips(SSXX, me, 3, th, tw, hN, hS, hW, hE, tid, false, true );
        write_strips(SSXY, me, 4, th, tw, hN, hS, hW, hE, tid, true,  true );
        if (tid < 64) __threadfence();
        __syncthreads();
        if (tid == 0) atomicExch(&g_flag[me], 2*t + 2);

#pragma unroll
        for (int k = 0; k < 3; k++) if (k < ncI)
            cellS(ic[k], SVY, SVX, SSYY, SSXX, SSXY, SMVYY, SMVYX, SMVXY, SMVXX);

        if (tid == 32 && hN){ volatile int* f = &g_flag[me-TS]; while (*f < 2*t+2) {} }
        if (tid == 64 && hS){ volatile int* f = &g_flag[me+TS]; while (*f < 2*t+2) {} }
        if (tid == 96 && hW){ volatile int* f = &g_flag[me-1 ]; while (*f < 2*t+2) {} }
        if (tid ==128 && hE){ volatile int* f = &g_flag[me+1 ]; while (*f < 2*t+2) {} }
        __syncthreads();

        read_halos(SSYY, me, 2, th, tw, hN, hS, hW, hE, tid, true,  false);
        read_halos(SSXX, me, 3, th, tw, hN, hS, hW, hE, tid, false, true );
        read_halos(SSXY, me, 4, th, tw, hN, hS, hW, hE, tid, true,  true );
        __syncthreads();
    }
}

// ---------------- launch ----------------
extern "C" void kernel_launch(void* const* d_in, const int* in_sizes, int n_in,
                              void* d_out, int out_size)
{
    const float* lamb = (const float*)d_in[0];
    const float* mu   = (const float*)d_in[1];
    const float* buo  = (const float*)d_in[2];
    const float* amp  = (const float*)d_in[3];
    const int*   sloc = (const int*)  d_in[4];
    const int*   rloc = (const int*)  d_in[5];
    float* out = (float*)d_out;

    static bool attr_set = false;
    if (!attr_set){
        cudaFuncSetAttribute(k_main, cudaFuncAttributeMaxDynamicSharedMemorySize, SMEM_BYTES);
        attr_set = true;
    }

    k_init<<<1, 128>>>();
    k_main<<<NB, NTHR, SMEM_BYTES>>>(lamb, mu, buo, amp, sloc, rloc, out);
}